// round 7
// baseline (speedup 1.0000x reference)
#include <cuda_runtime.h>
#include <cuda_fp16.h>
#include <cstdint>

#define NN   8192
#define FIN  256
#define FOUT 128
#define L2E  1.44269504f
#define LRA  0.2f
#define CK   64                    // j per chunk
#define JSPLIT 4
#define JBLK (NN / JSPLIT)         // 2048
#define NCH  (JBLK / CK)           // 32 chunks per block
#define RBLK 256                   // rows per block
#define NTI  (NN / CK)             // 128 prebuilt B tiles
#define TILE_BYTES 16384           // 64j x 128d x 2B (single fp16 term)

__device__ __align__(16)  float g_h[NN * FOUT];
__device__ float g_e1s[NN];        // 1.4427 * e1
__device__ float g_e2s[NN];        // 1.4427 * e2
__device__ __align__(128) unsigned char g_bt[(size_t)NTI * TILE_BYTES];  // 2MB
__device__ __align__(16)  float g_part[JSPLIT][NN * FOUT];               // 16MB
__device__ float g_psum[JSPLIT][NN];

// ------------------------- helpers -----------------------------------------
__device__ __forceinline__ uint32_t smem_u32(const void* p) {
    uint32_t a;
    asm("{ .reg .u64 t; cvta.to.shared.u64 t, %1; cvt.u32.u64 %0, t; }" : "=r"(a) : "l"(p));
    return a;
}
__device__ __forceinline__ uint32_t pack16(float lo, float hi) {
    uint32_t r;  // low 16 bits = lo (lower k index)
    asm("cvt.rn.f16x2.f32 %0, %1, %2;" : "=r"(r) : "f"(hi), "f"(lo));
    return r;
}
// mask-multiply: adj ints (0/1) -> fp16x2 {0,1} mask via 2 IMADs, one mul.f16x2
__device__ __forceinline__ uint32_t packmask(float lo, float hi, int ax, int ay) {
    uint32_t p = pack16(lo, hi);
    uint32_t m = (uint32_t)ax * 0x3C00u + (uint32_t)ay * 0x3C000000u;
    uint32_t r;
    asm("mul.f16x2 %0, %1, %2;" : "=r"(r) : "r"(p), "r"(m));
    return r;
}
__device__ __forceinline__ float pcalc(float se1, float se2) {
    float s = se1 + se2;
    s = fmaxf(s, LRA * s);          // lrelu commutes with positive scale
    float p;
    asm("ex2.approx.f32 %0, %1;" : "=f"(p) : "f"(s));
    return p;
}
__device__ __forceinline__ void mma16816(float* c, const uint32_t* a, const uint32_t* b) {
    asm volatile("mma.sync.aligned.m16n8k16.row.col.f32.f16.f16.f32 "
        "{%0,%1,%2,%3}, {%4,%5,%6,%7}, {%8,%9}, {%0,%1,%2,%3};"
        : "+f"(c[0]), "+f"(c[1]), "+f"(c[2]), "+f"(c[3])
        : "r"(a[0]), "r"(a[1]), "r"(a[2]), "r"(a[3]), "r"(b[0]), "r"(b[1]));
}
#define LDMX4(r, a) \
    asm volatile("ldmatrix.sync.aligned.m8n8.x4.shared.b16 {%0,%1,%2,%3}, [%4];" \
        : "=r"((r)[0]), "=r"((r)[1]), "=r"((r)[2]), "=r"((r)[3]) : "r"(a))
#define CP_ASYNC(dst, src) \
    asm volatile("cp.async.cg.shared.global [%0], [%1], 16;" :: "r"(dst), "l"(src))
#define CP_COMMIT() asm volatile("cp.async.commit_group;" ::: "memory")
#define CP_WAIT1()  asm volatile("cp.async.wait_group 1;"  ::: "memory")

// ---------------------------------------------------------------------------
// Kernel 1: h = x @ trans  (32-row tiles, 256 CTAs)
// ---------------------------------------------------------------------------
__global__ __launch_bounds__(256) void k_gemm_h(const float* __restrict__ x,
                                                const float* __restrict__ trans)
{
    __shared__ float xs[32 * 32];
    __shared__ float ts[32 * FOUT];
    const int t = threadIdx.x;
    const int rowbase = blockIdx.x * 32;
    const int ty = t >> 5;
    const int tx = t & 31;

    float acc[4][4];
    #pragma unroll
    for (int i = 0; i < 4; i++)
        #pragma unroll
        for (int c = 0; c < 4; c++) acc[i][c] = 0.f;

    const float4* x4 = (const float4*)x;
    const float4* t4 = (const float4*)trans;

    for (int k0 = 0; k0 < FIN; k0 += 32) {
        {
            int r = t >> 3, c = t & 7;
            ((float4*)xs)[r * 8 + c] = x4[(size_t)(rowbase + r) * (FIN/4) + (k0 >> 2) + c];
        }
        #pragma unroll
        for (int v = t, i = 0; i < 4; i++, v += 256) {
            int r = v >> 5, c = v & 31;
            ((float4*)ts)[r * 32 + c] = t4[(size_t)(k0 + r) * (FOUT/4) + c];
        }
        __syncthreads();
        #pragma unroll
        for (int kk = 0; kk < 32; kk++) {
            float4 b = *(const float4*)&ts[kk * FOUT + tx * 4];
            #pragma unroll
            for (int i = 0; i < 4; i++) {
                float a = xs[(ty * 4 + i) * 32 + kk];
                acc[i][0] += a * b.x; acc[i][1] += a * b.y;
                acc[i][2] += a * b.z; acc[i][3] += a * b.w;
            }
        }
        __syncthreads();
    }
    #pragma unroll
    for (int i = 0; i < 4; i++) {
        float4 o = make_float4(acc[i][0], acc[i][1], acc[i][2], acc[i][3]);
        *(float4*)&g_h[(size_t)(rowbase + ty * 4 + i) * FOUT + tx * 4] = o;
    }
}

// ---------------------------------------------------------------------------
// Kernel 2: e1/e2 (pre-scaled by log2(e))
// ---------------------------------------------------------------------------
__global__ __launch_bounds__(256) void k_e(const float* __restrict__ aw)
{
    const int row  = blockIdx.x * 8 + (threadIdx.x >> 5);
    const int lane = threadIdx.x & 31;
    float s1 = 0.f, s2 = 0.f;
    #pragma unroll
    for (int d = lane; d < FOUT; d += 32) {
        float v = g_h[(size_t)row * FOUT + d];
        s1 += v * aw[d];
        s2 += v * aw[FOUT + d];
    }
    #pragma unroll
    for (int o = 16; o; o >>= 1) {
        s1 += __shfl_xor_sync(0xFFFFFFFFu, s1, o);
        s2 += __shfl_xor_sync(0xFFFFFFFFu, s2, o);
    }
    if (lane == 0) { g_e1s[row] = s1 * L2E; g_e2s[row] = s2 * L2E; }
}

// ---------------------------------------------------------------------------
// Kernel 3 (prep): build B = h^T tiles (fp16) as ldmatrix-ready 8x8 blocks.
// blk = ((step*8+dpair)*2+dn)*2+kk; each blk = 128B: 8 rows (dr) x 8 j.
// Element (dr, jc) = h[j0+step*16+kk*8+jc][dp*16+dn*8+dr].
// ---------------------------------------------------------------------------
__global__ __launch_bounds__(256) void k_prep()
{
    const int tc = blockIdx.x;
    const int t  = threadIdx.x;
    const int j0 = tc * CK;
    unsigned char* tb = g_bt + (size_t)tc * TILE_BYTES;

    #pragma unroll
    for (int i = 0; i < 4; i++) {
        int rho = i * 256 + t;
        int blk = rho >> 3, dr = rho & 7;
        int kk = blk & 1, dn = (blk >> 1) & 1, dp = (blk >> 2) & 7, st = blk >> 5;
        int d  = dp * 16 + dn * 8 + dr;
        int jb = j0 + st * 16 + kk * 8;
        uint32_t h4[4];
        #pragma unroll
        for (int m = 0; m < 4; m++) {
            float a = g_h[(size_t)(jb + 2*m)     * FOUT + d];
            float b = g_h[(size_t)(jb + 2*m + 1) * FOUT + d];
            h4[m] = pack16(a, b);
        }
        *(uint4*)(tb + (uint32_t)blk * 128 + dr * 16) =
            make_uint4(h4[0], h4[1], h4[2], h4[3]);
    }
}

// ---------------------------------------------------------------------------
// Kernel 4 (main): fused masked-exp + fp16 HMMA attention GEMM.
// 256 threads = 8 warps, each m32 x n128 (two m16 row-groups share every
// B fragment -> half the LDSM traffic of the 16-warp m16 version).
// adj: direct int2 loads, mask via IMAD->fp16x2 multiply.
// Row sums via ones-column MMA per row-group. B double-buffered via cp.async.
// ---------------------------------------------------------------------------
__global__ __launch_bounds__(256, 1) void k_main(const int* __restrict__ adj)
{
    extern __shared__ unsigned char smem[];
    const uint32_t sb = smem_u32(smem);
    const int t = threadIdx.x, w = t >> 5, l = t & 31;
    const int bx = blockIdx.x, by = blockIdx.y;
    const int g = l >> 2, qh = l & 3, q2 = qh * 2;
    const int rowb = bx * RBLK + w * 32;
    const size_t jbase = (size_t)by * JBLK;

    // prime B double-buffer (2 x 16KB, 256 threads -> 4 vec16 each per buf)
    const unsigned char* bt0 = g_bt + (size_t)(by * NCH) * TILE_BYTES;
    #pragma unroll
    for (int c = 0; c < 2; c++) {
        uint32_t dst = sb + c * TILE_BYTES + t * 16;
        const unsigned char* src = bt0 + (size_t)c * TILE_BYTES + t * 16;
        #pragma unroll
        for (int i = 0; i < 4; i++) CP_ASYNC(dst + i * 4096, src + i * 4096);
        CP_COMMIT();
    }

    const float se1a = g_e1s[rowb + g];
    const float se1b = g_e1s[rowb + g + 8];
    const float se1c = g_e1s[rowb + g + 16];
    const float se1d = g_e1s[rowb + g + 24];
    const int* pa = adj + (size_t)(rowb + g)      * NN + jbase;
    const int* pb_ = adj + (size_t)(rowb + g + 8)  * NN + jbase;
    const int* pc = adj + (size_t)(rowb + g + 16) * NN + jbase;
    const int* pd = adj + (size_t)(rowb + g + 24) * NN + jbase;

    float c0_[16][4], c1_[16][4];
    #pragma unroll
    for (int td = 0; td < 16; td++)
        #pragma unroll
        for (int k = 0; k < 4; k++) { c0_[td][k] = 0.f; c1_[td][k] = 0.f; }
    float crs0[4] = {0.f, 0.f, 0.f, 0.f};
    float crs1[4] = {0.f, 0.f, 0.f, 0.f};
    const uint32_t bones[2] = {0x3C003C00u, 0x3C003C00u};

    // adj prefetch for (c=0, s=0): rows a,b,c,d x (j q2, q2+8)
    size_t joff = q2;
    int2 va0 = __ldg((const int2*)(pa + joff)),  va1 = __ldg((const int2*)(pa + joff + 8));
    int2 vb0 = __ldg((const int2*)(pb_ + joff)), vb1 = __ldg((const int2*)(pb_ + joff + 8));
    int2 vc0 = __ldg((const int2*)(pc + joff)),  vc1 = __ldg((const int2*)(pc + joff + 8));
    int2 vd0 = __ldg((const int2*)(pd + joff)),  vd1 = __ldg((const int2*)(pd + joff + 8));

    for (int c = 0; c < NCH; c++) {
        CP_WAIT1();
        __syncthreads();
        const uint32_t bufb = sb + (c & 1) * TILE_BYTES;

        #pragma unroll
        for (int s = 0; s < 4; s++) {
            const float2 e2a = *(const float2*)(g_e2s + jbase + joff);
            const float2 e2b = *(const float2*)(g_e2s + jbase + joff + 8);

            // snapshot adj regs, then prefetch next step
            const int2 ba0 = va0, ba1 = va1, bb0 = vb0, bb1 = vb1;
            const int2 bc0 = vc0, bc1 = vc1, bd0 = vd0, bd1 = vd1;
            if (!(c == NCH - 1 && s == 3)) {
                joff += 16;
                va0 = __ldg((const int2*)(pa + joff));  va1 = __ldg((const int2*)(pa + joff + 8));
                vb0 = __ldg((const int2*)(pb_ + joff)); vb1 = __ldg((const int2*)(pb_ + joff + 8));
                vc0 = __ldg((const int2*)(pc + joff));  vc1 = __ldg((const int2*)(pc + joff + 8));
                vd0 = __ldg((const int2*)(pd + joff));  vd1 = __ldg((const int2*)(pd + joff + 8));
            }

            // 16 exps (one per (row, j) this lane owns), fp16 pack + mask
            uint32_t a0[4], a1[4];
            a0[0] = packmask(pcalc(se1a, e2a.x), pcalc(se1a, e2a.y), ba0.x, ba0.y);
            a0[1] = packmask(pcalc(se1b, e2a.x), pcalc(se1b, e2a.y), bb0.x, bb0.y);
            a0[2] = packmask(pcalc(se1a, e2b.x), pcalc(se1a, e2b.y), ba1.x, ba1.y);
            a0[3] = packmask(pcalc(se1b, e2b.x), pcalc(se1b, e2b.y), bb1.x, bb1.y);
            a1[0] = packmask(pcalc(se1c, e2a.x), pcalc(se1c, e2a.y), bc0.x, bc0.y);
            a1[1] = packmask(pcalc(se1d, e2a.x), pcalc(se1d, e2a.y), bd0.x, bd0.y);
            a1[2] = packmask(pcalc(se1c, e2b.x), pcalc(se1c, e2b.y), bc1.x, bc1.y);
            a1[3] = packmask(pcalc(se1d, e2b.x), pcalc(se1d, e2b.y), bd1.x, bd1.y);

            #pragma unroll
            for (int dp = 0; dp < 8; dp++) {
                uint32_t bh[4];
                const uint32_t ad = bufb + (s * 8 + dp) * 512
                                  + (l >> 3) * 128 + (l & 7) * 16;
                LDMX4(bh, ad);
                mma16816(c0_[2 * dp],     a0, bh);
                mma16816(c0_[2 * dp + 1], a0, bh + 2);
                mma16816(c1_[2 * dp],     a1, bh);
                mma16816(c1_[2 * dp + 1], a1, bh + 2);
            }
            mma16816(crs0, a0, bones);
            mma16816(crs1, a1, bones);
        }

        __syncthreads();
        if (c + 2 < NCH) {
            uint32_t dst = sb + (c & 1) * TILE_BYTES + t * 16;
            const unsigned char* src = bt0 + (size_t)(c + 2) * TILE_BYTES + t * 16;
            #pragma unroll
            for (int i = 0; i < 4; i++) CP_ASYNC(dst + i * 4096, src + i * 4096);
        }
        CP_COMMIT();
    }

    // row sums (all n cols identical in crs; qh==0 lanes write)
    if (qh == 0) {
        g_psum[by][rowb + g]      = crs0[0];
        g_psum[by][rowb + g + 8]  = crs0[2];
        g_psum[by][rowb + g + 16] = crs1[0];
        g_psum[by][rowb + g + 24] = crs1[2];
    }

    // store unnormalized partials
    float* pp = g_part[by];
    #pragma unroll
    for (int td = 0; td < 16; td++) {
        const int col = td * 8 + q2;
        *(float2*)(pp + (size_t)(rowb + g) * FOUT + col) =
            make_float2(c0_[td][0], c0_[td][1]);
        *(float2*)(pp + (size_t)(rowb + g + 8) * FOUT + col) =
            make_float2(c0_[td][2], c0_[td][3]);
        *(float2*)(pp + (size_t)(rowb + g + 16) * FOUT + col) =
            make_float2(c1_[td][0], c1_[td][1]);
        *(float2*)(pp + (size_t)(rowb + g + 24) * FOUT + col) =
            make_float2(c1_[td][2], c1_[td][3]);
    }
}

// ---------------------------------------------------------------------------
// Kernel 5 (final): combine j-split partials, normalize, ELU.
// ---------------------------------------------------------------------------
__global__ __launch_bounds__(256) void k_final(float* __restrict__ out)
{
    const int idx = blockIdx.x * 256 + threadIdx.x;   // float4 index
    const int r = idx >> 5;
    float4 v = make_float4(0.f, 0.f, 0.f, 0.f);
    #pragma unroll
    for (int p = 0; p < JSPLIT; p++) {
        float4 a = ((const float4*)g_part[p])[idx];
        v.x += a.x; v.y += a.y; v.z += a.z; v.w += a.w;
    }
    const float inv = 1.f / (g_psum[0][r] + g_psum[1][r] + g_psum[2][r] + g_psum[3][r]);
    float o[4] = { v.x * inv, v.y * inv, v.z * inv, v.w * inv };
    #pragma unroll
    for (int i = 0; i < 4; i++) o[i] = o[i] > 0.f ? o[i] : expm1f(o[i]);
    ((float4*)out)[idx] = make_float4(o[0], o[1], o[2], o[3]);
}

// ---------------------------------------------------------------------------
extern "C" void kernel_launch(void* const* d_in, const int* in_sizes, int n_in,
                              void* d_out, int out_size)
{
    const float* x     = (const float*)d_in[0];
    const int*   adj   = (const int*)d_in[1];
    const float* trans = (const float*)d_in[2];
    const float* aw    = (const float*)d_in[3];
    float*       out   = (float*)d_out;

    const int smem_bytes = 2 * TILE_BYTES;   // 32KB
    cudaFuncSetAttribute(k_main, cudaFuncAttributeMaxDynamicSharedMemorySize, smem_bytes);

    k_gemm_h<<<NN / 32, 256>>>(x, trans);
    k_e<<<NN / 8, 256>>>(aw);
    k_prep<<<NTI, 256>>>();
    dim3 gmain(NN / RBLK, JSPLIT);
    k_main<<<gmain, 256, smem_bytes>>>(adj);
    k_final<<<NN * FOUT / (256 * 4), 256>>>(out);
}